// round 8
// baseline (speedup 1.0000x reference)
#include <cuda_runtime.h>
#include <cstdint>
#include <math.h>

#define BB 16
#define TT 500
#define CC 2048
#define SN 64
#define SD 512
#define CLU 8                      // CTAs per den cluster
#define CPC (SD / CLU)             // 64 columns per den CTA

typedef unsigned long long ull;

__device__ float g_llh[2 * BB];    // [0..15] den, [16..31] num

__device__ __forceinline__ float warp_max(float v) {
#pragma unroll
    for (int o = 16; o > 0; o >>= 1) v = fmaxf(v, __shfl_xor_sync(0xffffffffu, v, o));
    return v;
}
__device__ __forceinline__ float warp_sum(float v) {
#pragma unroll
    for (int o = 16; o > 0; o >>= 1) v += __shfl_xor_sync(0xffffffffu, v, o);
    return v;
}
__device__ __forceinline__ float clip30(float v) {
    return fminf(fmaxf(v, -30.f), 30.f);
}
__device__ __forceinline__ uint32_t smem_u32(const void* p) {
    uint32_t a;
    asm("{ .reg .u64 t; cvta.to.shared.u64 t, %1; cvt.u32.u64 %0, t; }" : "=r"(a) : "l"(p));
    return a;
}
// inline mapa + remote store (proven pattern), f32 and u64 widths
__device__ __forceinline__ void st_cluster_f32(uint32_t local_addr, int rank, float v) {
    uint32_t rem;
    asm volatile("mapa.shared::cluster.u32 %0, %1, %2;" : "=r"(rem) : "r"(local_addr), "r"(rank));
    asm volatile("st.shared::cluster.f32 [%0], %1;" :: "r"(rem), "f"(v) : "memory");
}
__device__ __forceinline__ void st_cluster_u64(uint32_t local_addr, int rank, ull v) {
    uint32_t rem;
    asm volatile("mapa.shared::cluster.u32 %0, %1, %2;" : "=r"(rem) : "r"(local_addr), "r"(rank));
    asm volatile("st.shared::cluster.u64 [%0], %1;" :: "r"(rem), "l"(v) : "memory");
}
__device__ __forceinline__ void mbar_init(uint32_t addr, uint32_t cnt) {
    asm volatile("mbarrier.init.shared.b64 [%0], %1;" :: "r"(addr), "r"(cnt) : "memory");
}
__device__ __forceinline__ void mbar_arrive_remote(uint32_t local_mbar, int rank) {
    uint32_t rem;
    asm volatile("mapa.shared::cluster.u32 %0, %1, %2;" : "=r"(rem) : "r"(local_mbar), "r"(rank));
    asm volatile("mbarrier.arrive.release.cluster.shared::cluster.b64 _, [%0];" :: "r"(rem) : "memory");
}
__device__ __forceinline__ void fence_acqrel_cluster_() {
    asm volatile("fence.acq_rel.cluster;" ::: "memory");
}
__device__ __forceinline__ void mbar_wait_parity(uint32_t mbar, uint32_t parity) {
    asm volatile(
        "{\n\t"
        ".reg .pred P1;\n\t"
        "WAIT_LOOP_%=:\n\t"
        "mbarrier.try_wait.parity.acquire.cluster.shared::cta.b64 P1, [%0], %1, 0x989680;\n\t"
        "@P1 bra.uni WAIT_DONE_%=;\n\t"
        "bra.uni WAIT_LOOP_%=;\n\t"
        "WAIT_DONE_%=:\n\t"
        "}"
        :: "r"(mbar), "r"(parity) : "memory");
}
__device__ __forceinline__ void cluster_sync_() {
    asm volatile("barrier.cluster.arrive.aligned;" ::: "memory");
    asm volatile("barrier.cluster.wait.aligned;" ::: "memory");
}
__device__ __forceinline__ uint32_t ctarank_() {
    uint32_t r;
    asm("mov.u32 %0, %%cluster_ctarank;" : "=r"(r));
    return r;
}
// packed dual-fp32 fma: d = a * b + d
__device__ __forceinline__ void fma2(ull& d, ull a, ull b) {
    asm("fma.rn.f32x2 %0, %1, %2, %0;" : "+l"(d) : "l"(a), "l"(b));
}

// ---------------------------------------------------------------------------
// Denominator: one 8-CTA cluster per batch, linear state, minimal sync:
// per step = 1 mbarrier wait + 1 __syncthreads.
// Producers push state PRE-DUPLICATED as {w,w} u64 into peers' packed buffer;
// output-side normalization: w_t = (sum w_{t-1} P) * (1/m_{t-1}) * E_t.
// ---------------------------------------------------------------------------
__device__ void den_path(const float* __restrict__ x, const int* __restrict__ seqlens,
                         const float* __restrict__ logA, const float* __restrict__ ls,
                         const float* __restrict__ lf, const int* __restrict__ ids_g) {
    __shared__ __align__(16) ull u2buf[2][SD];       // packed {w,w}, double-buffered
    __shared__ __align__(16) ull red2[16 * 32];      // [rg][cp] -> cols {2cp,2cp+1}
    __shared__ float m_arr[2][16];                   // 8 CTAs x 2 producer warps
    __shared__ __align__(8) ull mbar[2];             // data-ready barriers
    __shared__ float warp_red[16];

    const int tid  = threadIdx.x;
    const int lane = tid & 31, wid = tid >> 5;
    const int rg   = tid >> 5;          // row group 0..15 (32 rows each)
    const int cp   = tid & 31;          // column pair 0..31
    const int r    = (int)ctarank_();
    const int b    = blockIdx.x / CLU;
    const int j0   = r * CPC + 2 * cp;
    const int L    = seqlens[b];
    const float* xb = x + (size_t)b * TT * CC;

    // P slice in registers, packed per column pair
    ull pr[32];
#pragma unroll
    for (int k = 0; k < 32; ++k) {
        float2 p2;
        p2.x = __expf(logA[(size_t)(rg * 32 + k) * SD + j0]);
        p2.y = __expf(logA[(size_t)(rg * 32 + k) * SD + j0 + 1]);
        pr[k] = *(ull*)&p2;
    }

    if (tid == 0) {
        mbar_init(smem_u32(&mbar[0]), 16);   // 2 producer warps x 8 CTAs
        mbar_init(smem_u32(&mbar[1]), 16);
    }
    __syncthreads();
    cluster_sync_();    // all mbarrier inits visible before any arrive

    // t = 0 init (threads 0..63 own this CTA's 64 columns)
    int myid = 0;
    float emn = 0.f, logC = 0.f;
    const int jcol = r * CPC + tid;     // valid when tid < 64
    if (tid < 64) {
        myid = ids_g[jcol];
        float w0 = __expf(ls[jcol] + clip30(xb[myid]));
        float2 ww = make_float2(w0, w0);
        ull wp = *(ull*)&ww;
#pragma unroll
        for (int q = 0; q < CLU; ++q)
            st_cluster_u64(smem_u32(&u2buf[0][jcol]), q, wp);
        float wm = warp_max(w0);
        if (lane == 0) {
#pragma unroll
            for (int q = 0; q < CLU; ++q)
                st_cluster_f32(smem_u32(&m_arr[0][r * 2 + wid]), q, wm);
        }
        __syncwarp();
        if (lane == 0) {
            fence_acqrel_cluster_();
#pragma unroll
            for (int q = 0; q < CLU; ++q)
                mbar_arrive_remote(smem_u32(&mbar[0]), q);
        }
        emn = (L > 1) ? xb[CC + myid] : 0.f;
    }

    int p = 0;
    unsigned uc0 = 0, uc1 = 0;          // use counters -> phase parity
    for (int t = 1; t < L; ++t) {
        unsigned par = p ? (uc1++ & 1u) : (uc0++ & 1u);
        mbar_wait_parity(smem_u32(&mbar[p]), par);

        // matvec partial: 32 rows x 2 cols, packed f32x2, direct on u2buf[p]
        ull acc = 0ull;
        const ulonglong2* uu = (const ulonglong2*)&u2buf[p][rg * 32];
#pragma unroll
        for (int k2 = 0; k2 < 16; ++k2) {
            ulonglong2 u = uu[k2];
            fma2(acc, u.x, pr[2 * k2]);
            fma2(acc, u.y, pr[2 * k2 + 1]);
        }
        red2[rg * 32 + cp] = acc;
        float E = 0.f;
        if (tid < 64) {
            E = __expf(clip30(emn));
            if (t + 1 < L) emn = xb[(size_t)(t + 1) * CC + myid];
        }
        __syncthreads();

        if (tid < 64) {
            // combine the 16 lagged warp maxima (input-state max)
            float m01 = fmaxf(m_arr[p][0], m_arr[p][1]);
            float m23 = fmaxf(m_arr[p][2], m_arr[p][3]);
            float m45 = fmaxf(m_arr[p][4], m_arr[p][5]);
            float m67 = fmaxf(m_arr[p][6], m_arr[p][7]);
            float m89 = fmaxf(m_arr[p][8], m_arr[p][9]);
            float mab = fmaxf(m_arr[p][10], m_arr[p][11]);
            float mcd = fmaxf(m_arr[p][12], m_arr[p][13]);
            float mef = fmaxf(m_arr[p][14], m_arr[p][15]);
            float m = fmaxf(fmaxf(fmaxf(m01, m23), fmaxf(m45, m67)),
                            fmaxf(fmaxf(m89, mab), fmaxf(mcd, mef)));
            float sc = __fdividef(1.0f, m);
            // reduce 16 partials (4-way trees)
            const float* rf = (const float*)red2;
            float v0 = 0.f, v1 = 0.f, v2 = 0.f, v3 = 0.f;
#pragma unroll
            for (int g2 = 0; g2 < 4; ++g2) {
                v0 += rf[(4 * g2 + 0) * 64 + tid];
                v1 += rf[(4 * g2 + 1) * 64 + tid];
                v2 += rf[(4 * g2 + 2) * 64 + tid];
                v3 += rf[(4 * g2 + 3) * 64 + tid];
            }
            float v = (v0 + v1) + (v2 + v3);
            float w = (v * sc) * E;          // bounded: v*sc <= 512, *E <= 5.4e15
            float2 ww = make_float2(w, w);
            ull wp2 = *(ull*)&ww;
#pragma unroll
            for (int q = 0; q < CLU; ++q)
                st_cluster_u64(smem_u32(&u2buf[1 - p][jcol]), q, wp2);
            float wm = warp_max(w);
            if (lane == 0) {
#pragma unroll
                for (int q = 0; q < CLU; ++q)
                    st_cluster_f32(smem_u32(&m_arr[1 - p][r * 2 + wid]), q, wm);
            }
            __syncwarp();
            if (lane == 0) {
                fence_acqrel_cluster_();
#pragma unroll
                for (int q = 0; q < CLU; ++q)
                    mbar_arrive_remote(smem_u32(&mbar[1 - p]), q);
            }
            if (tid == 0) logC += __logf(m);
        }
        p ^= 1;
    }

    // wait for the final state, then rank 0 finishes
    {
        unsigned par = p ? (uc1++ & 1u) : (uc0++ & 1u);
        mbar_wait_parity(smem_u32(&mbar[p]), par);
    }
    if (r == 0) {
        float w = __uint_as_float((uint32_t)u2buf[p][tid]);   // low half
        float e = w * __expf(lf[tid]);
        float ws = warp_sum(e);
        if (lane == 0) warp_red[wid] = ws;
        __syncthreads();
        if (tid == 0) {
            float s = 0.f;
            for (int i = 0; i < 16; ++i) s += warp_red[i];
            g_llh[b] = logC + __logf(s);
        }
    }
    cluster_sync_();   // no CTA exits while peers may still receive DSMEM traffic
}

// ---------------------------------------------------------------------------
// Numerator: per-batch FSM (S=64), linear state, one CTA per batch (hidden).
// ---------------------------------------------------------------------------
__device__ void num_path(int b, const float* __restrict__ x,
                         const int* __restrict__ seqlens,
                         const float* __restrict__ logA,
                         const float* __restrict__ ls,
                         const float* __restrict__ lf,
                         const int* __restrict__ ids_g) {
    __shared__ __align__(16) float Pn[SN * SN];
    __shared__ float w_n[SN];
    __shared__ float redn[8][SN];
    __shared__ float wred[2];

    const int tid = threadIdx.x;
    const int lane = tid & 31;
    const int g = tid >> 6;              // row group 0..7 (8 rows each)
    const int col = tid & 63;
    const int L = seqlens[b];
    const float* xb = x + (size_t)b * TT * CC;

    for (int i = tid; i < SN * SN; i += 512)
        Pn[i] = __expf(logA[(size_t)b * SN * SN + i]);

    int myid = 0;
    float emn = 0.f, logC = 0.f;
    if (tid < SN) {
        myid = ids_g[b * SN + tid];
        float w0 = __expf(ls[b * SN + tid] + clip30(xb[myid]));
        w_n[tid] = w0;
        float wm = warp_max(w0);
        if (lane == 0) wred[tid >> 5] = wm;
        emn = (L > 1) ? xb[CC + myid] : 0.f;
    }
    __syncthreads();

    for (int t = 1; t < L; ++t) {
        float m = fmaxf(wred[0], wred[1]);
        float E = 0.f, sc = 0.f;
        if (tid < SN) {
            sc = __fdividef(1.0f, m);
            E = __expf(clip30(emn));
            if (t + 1 < L) emn = xb[(size_t)(t + 1) * CC + myid];
        }
        float acc = 0.f;
#pragma unroll
        for (int k = 0; k < 8; ++k)
            acc = fmaf(w_n[g * 8 + k], Pn[(g * 8 + k) * SN + col], acc);
        redn[g][col] = acc;
        __syncthreads();
        if (tid < SN) {
            float v = 0.f;
#pragma unroll
            for (int g2 = 0; g2 < 8; ++g2) v += redn[g2][tid];
            float w = (v * sc) * E;
            w_n[tid] = w;
            float wm = warp_max(w);
            if (lane == 0) wred[tid >> 5] = wm;
            if (tid == 0) logC += __logf(m);
        }
        __syncthreads();
    }

    if (tid < SN) {
        float e = w_n[tid] * __expf(lf[b * SN + tid]);
        float ws = warp_sum(e);
        if (lane == 0) wred[tid >> 5] = ws;
    }
    __syncthreads();
    if (tid == 0) g_llh[BB + b] = logC + __logf(wred[0] + wred[1]);
}

// Fused: clusters 0..15 (CTAs 0..127) = den; CTAs 128..143 = num batches 0..15.
__global__ void __launch_bounds__(512, 1) __cluster_dims__(CLU, 1, 1)
fused_kernel(const float* __restrict__ x, const int* __restrict__ seqlens,
             const float* __restrict__ num_logA, const float* __restrict__ num_ls,
             const float* __restrict__ num_lf, const int* __restrict__ num_ids,
             const float* __restrict__ den_logA, const float* __restrict__ den_ls,
             const float* __restrict__ den_lf, const int* __restrict__ den_ids) {
    if (blockIdx.x < BB * CLU)
        den_path(x, seqlens, den_logA, den_ls, den_lf, den_ids);
    else
        num_path(blockIdx.x - BB * CLU, x, seqlens, num_logA, num_ls, num_lf, num_ids);
}

__global__ void finalize_kernel(float* __restrict__ out) {
    float sden = 0.f, snum = 0.f;
    for (int i = 0; i < BB; ++i) {
        sden += g_llh[i];
        snum += g_llh[BB + i];
    }
    out[0] = -(snum - sden);
}

extern "C" void kernel_launch(void* const* d_in, const int* in_sizes, int n_in,
                              void* d_out, int out_size) {
    const float* x        = (const float*)d_in[0];
    const int*   seqlens  = (const int*)d_in[1];
    const float* num_logA = (const float*)d_in[2];
    const float* num_ls   = (const float*)d_in[3];
    const float* num_lf   = (const float*)d_in[4];
    const int*   num_ids  = (const int*)d_in[5];
    const float* den_logA = (const float*)d_in[6];
    const float* den_ls   = (const float*)d_in[7];
    const float* den_lf   = (const float*)d_in[8];
    const int*   den_ids  = (const int*)d_in[9];

    fused_kernel<<<BB * CLU + BB, 512>>>(x, seqlens, num_logA, num_ls, num_lf,
                                         num_ids, den_logA, den_ls, den_lf, den_ids);
    finalize_kernel<<<1, 1>>>((float*)d_out);
}

// round 9
// speedup vs baseline: 1.8953x; 1.8953x over previous
#include <cuda_runtime.h>
#include <cstdint>
#include <math.h>

#define BB 16
#define TT 500
#define CC 2048
#define SN 64
#define SD 512
#define CLU 8                      // CTAs per den cluster
#define CPC (SD / CLU)             // 64 columns per den CTA

typedef unsigned long long ull;

__device__ float g_llh[2 * BB];    // [0..15] den, [16..31] num

__device__ __forceinline__ float warp_max(float v) {
#pragma unroll
    for (int o = 16; o > 0; o >>= 1) v = fmaxf(v, __shfl_xor_sync(0xffffffffu, v, o));
    return v;
}
__device__ __forceinline__ float warp_sum(float v) {
#pragma unroll
    for (int o = 16; o > 0; o >>= 1) v += __shfl_xor_sync(0xffffffffu, v, o);
    return v;
}
__device__ __forceinline__ float clip30(float v) {
    return fminf(fmaxf(v, -30.f), 30.f);
}
__device__ __forceinline__ uint32_t smem_u32(const void* p) {
    uint32_t a;
    asm("{ .reg .u64 t; cvta.to.shared.u64 t, %1; cvt.u32.u64 %0, t; }" : "=r"(a) : "l"(p));
    return a;
}
// inline mapa + remote store (proven pattern)
__device__ __forceinline__ void st_cluster_f32(uint32_t local_addr, int rank, float v) {
    uint32_t rem;
    asm volatile("mapa.shared::cluster.u32 %0, %1, %2;" : "=r"(rem) : "r"(local_addr), "r"(rank));
    asm volatile("st.shared::cluster.f32 [%0], %1;" :: "r"(rem), "f"(v) : "memory");
}
__device__ __forceinline__ void st_cluster_u64(uint32_t local_addr, int rank, ull v) {
    uint32_t rem;
    asm volatile("mapa.shared::cluster.u32 %0, %1, %2;" : "=r"(rem) : "r"(local_addr), "r"(rank));
    asm volatile("st.shared::cluster.u64 [%0], %1;" :: "r"(rem), "l"(v) : "memory");
}
__device__ __forceinline__ void cluster_sync_() {
    asm volatile("barrier.cluster.arrive.aligned;" ::: "memory");
    asm volatile("barrier.cluster.wait.aligned;" ::: "memory");
}
__device__ __forceinline__ uint32_t ctarank_() {
    uint32_t r;
    asm("mov.u32 %0, %%cluster_ctarank;" : "=r"(r));
    return r;
}
// packed dual-fp32 fma: d = a * b + d
__device__ __forceinline__ void fma2(ull& d, ull a, ull b) {
    asm("fma.rn.f32x2 %0, %1, %2, %0;" : "+l"(d) : "l"(a), "l"(b));
}

// ---------------------------------------------------------------------------
// Denominator: one 8-CTA cluster per batch, linear state.
// ALL 512 threads produce: thread (q=tid>>6, col=tid&63) reduces the 16
// matvec partials for col (redundant x8), computes w, and issues exactly ONE
// remote u64 store {w,w} to rank q. Per step: matvec -> bar -> finalize/push
// -> cluster.sync. Output-side normalization with lagged max broadcast.
// ---------------------------------------------------------------------------
__device__ void den_path(const float* __restrict__ x, const int* __restrict__ seqlens,
                         const float* __restrict__ logA, const float* __restrict__ ls,
                         const float* __restrict__ lf, const int* __restrict__ ids_g) {
    __shared__ __align__(16) ull u2buf[2][SD];       // packed {w,w}, double-buffered
    __shared__ __align__(16) ull red2[16 * 32];      // [rg][cp] -> cols {2cp,2cp+1}
    __shared__ float m_arr[2][16];                   // [src CTA r][col half]
    __shared__ float warp_red[16];

    const int tid  = threadIdx.x;
    const int lane = tid & 31, wid = tid >> 5;
    const int rg   = tid >> 5;          // matvec row group 0..15 (32 rows each)
    const int cp   = tid & 31;          // matvec column pair 0..31
    const int col  = tid & 63;          // finalize: local column
    const int q    = tid >> 6;          // finalize: destination rank
    const int half = (tid >> 5) & 1;    // which 32-col half of the slice
    const int r    = (int)ctarank_();
    const int b    = blockIdx.x / CLU;
    const int j0   = r * CPC + 2 * cp;
    const int L    = seqlens[b];
    const float* xb = x + (size_t)b * TT * CC;

    // P slice in registers, packed per column pair
    ull pr[32];
#pragma unroll
    for (int k = 0; k < 32; ++k) {
        float2 p2;
        p2.x = __expf(logA[(size_t)(rg * 32 + k) * SD + j0]);
        p2.y = __expf(logA[(size_t)(rg * 32 + k) * SD + j0 + 1]);
        pr[k] = *(ull*)&p2;
    }

    // Every thread owns one (col, q) pair for the push phase.
    const int jcol = r * CPC + col;
    const int myid = ids_g[jcol];

    // t = 0 init: all threads compute w0 for their col, push to their rank.
    {
        float w0 = __expf(ls[jcol] + clip30(xb[myid]));
        st_cluster_u64(smem_u32(&u2buf[0][jcol]), q, *(ull*)&make_float2(w0, w0));
        float wm = warp_max(w0);     // warp covers 32 distinct cols (one half)
        if (lane == 0)
            st_cluster_f32(smem_u32(&m_arr[0][r * 2 + half]), q, wm);
    }
    float emn = (L > 1) ? xb[CC + myid] : 0.f;
    float logC = 0.f;
    cluster_sync_();

    int p = 0;
    for (int t = 1; t < L; ++t) {
        // matvec partial: 32 rows x 2 cols, packed f32x2, direct on u2buf[p]
        ull acc = 0ull;
        const ulonglong2* uu = (const ulonglong2*)&u2buf[p][rg * 32];
#pragma unroll
        for (int k2 = 0; k2 < 16; ++k2) {
            ulonglong2 u = uu[k2];
            fma2(acc, u.x, pr[2 * k2]);
            fma2(acc, u.y, pr[2 * k2 + 1]);
        }
        red2[rg * 32 + cp] = acc;
        // overlap: per-thread E and lagged-max combine (broadcast LDS reads)
        float E = __expf(clip30(emn));
        if (t + 1 < L) emn = xb[(size_t)(t + 1) * CC + myid];
        float m = m_arr[p][0];
#pragma unroll
        for (int i = 1; i < 16; ++i) m = fmaxf(m, m_arr[p][i]);
        float sc = __fdividef(1.0f, m);
        __syncthreads();

        // finalize: reduce 16 partials for my col (redundant x8), one push
        const float* rf = (const float*)red2;
        float v0 = 0.f, v1 = 0.f, v2 = 0.f, v3 = 0.f;
#pragma unroll
        for (int g2 = 0; g2 < 4; ++g2) {
            v0 += rf[(4 * g2 + 0) * 64 + col];
            v1 += rf[(4 * g2 + 1) * 64 + col];
            v2 += rf[(4 * g2 + 2) * 64 + col];
            v3 += rf[(4 * g2 + 3) * 64 + col];
        }
        float w = (((v0 + v1) + (v2 + v3)) * sc) * E;   // bounded in fp32
        st_cluster_u64(smem_u32(&u2buf[1 - p][jcol]), q, *(ull*)&make_float2(w, w));
        float wm = warp_max(w);
        if (lane == 0)
            st_cluster_f32(smem_u32(&m_arr[1 - p][r * 2 + half]), q, wm);
        if (tid == 0) logC += __logf(m);
        cluster_sync_();
        p ^= 1;
    }

    // llh = logC + log(sum_j w[j] * exp(lf[j]));  rank 0 has full w
    if (r == 0) {
        float w = __uint_as_float((uint32_t)u2buf[p][tid]);   // low half
        float e = w * __expf(lf[tid]);
        float ws = warp_sum(e);
        if (lane == 0) warp_red[wid] = ws;
        __syncthreads();
        if (tid == 0) {
            float s = 0.f;
            for (int i = 0; i < 16; ++i) s += warp_red[i];
            g_llh[b] = logC + __logf(s);
        }
    }
    cluster_sync_();   // no CTA exits while peers may still receive DSMEM traffic
}

// ---------------------------------------------------------------------------
// Numerator: per-batch FSM (S=64), linear state, one CTA per batch (hidden).
// ---------------------------------------------------------------------------
__device__ void num_path(int b, const float* __restrict__ x,
                         const int* __restrict__ seqlens,
                         const float* __restrict__ logA,
                         const float* __restrict__ ls,
                         const float* __restrict__ lf,
                         const int* __restrict__ ids_g) {
    __shared__ __align__(16) float Pn[SN * SN];
    __shared__ float w_n[SN];
    __shared__ float redn[8][SN];
    __shared__ float wred[2];

    const int tid = threadIdx.x;
    const int lane = tid & 31;
    const int g = tid >> 6;              // row group 0..7 (8 rows each)
    const int col = tid & 63;
    const int L = seqlens[b];
    const float* xb = x + (size_t)b * TT * CC;

    for (int i = tid; i < SN * SN; i += 512)
        Pn[i] = __expf(logA[(size_t)b * SN * SN + i]);

    int myid = 0;
    float emn = 0.f, logC = 0.f;
    if (tid < SN) {
        myid = ids_g[b * SN + tid];
        float w0 = __expf(ls[b * SN + tid] + clip30(xb[myid]));
        w_n[tid] = w0;
        float wm = warp_max(w0);
        if (lane == 0) wred[tid >> 5] = wm;
        emn = (L > 1) ? xb[CC + myid] : 0.f;
    }
    __syncthreads();

    for (int t = 1; t < L; ++t) {
        float m = fmaxf(wred[0], wred[1]);
        float E = 0.f, sc = 0.f;
        if (tid < SN) {
            sc = __fdividef(1.0f, m);
            E = __expf(clip30(emn));
            if (t + 1 < L) emn = xb[(size_t)(t + 1) * CC + myid];
        }
        float acc = 0.f;
#pragma unroll
        for (int k = 0; k < 8; ++k)
            acc = fmaf(w_n[g * 8 + k], Pn[(g * 8 + k) * SN + col], acc);
        redn[g][col] = acc;
        __syncthreads();
        if (tid < SN) {
            float v = 0.f;
#pragma unroll
            for (int g2 = 0; g2 < 8; ++g2) v += redn[g2][tid];
            float w = (v * sc) * E;
            w_n[tid] = w;
            float wm = warp_max(w);
            if (lane == 0) wred[tid >> 5] = wm;
            if (tid == 0) logC += __logf(m);
        }
        __syncthreads();
    }

    if (tid < SN) {
        float e = w_n[tid] * __expf(lf[b * SN + tid]);
        float ws = warp_sum(e);
        if (lane == 0) wred[tid >> 5] = ws;
    }
    __syncthreads();
    if (tid == 0) g_llh[BB + b] = logC + __logf(wred[0] + wred[1]);
}

// Fused: clusters 0..15 (CTAs 0..127) = den; CTAs 128..143 = num batches 0..15.
__global__ void __launch_bounds__(512, 1) __cluster_dims__(CLU, 1, 1)
fused_kernel(const float* __restrict__ x, const int* __restrict__ seqlens,
             const float* __restrict__ num_logA, const float* __restrict__ num_ls,
             const float* __restrict__ num_lf, const int* __restrict__ num_ids,
             const float* __restrict__ den_logA, const float* __restrict__ den_ls,
             const float* __restrict__ den_lf, const int* __restrict__ den_ids) {
    if (blockIdx.x < BB * CLU)
        den_path(x, seqlens, den_logA, den_ls, den_lf, den_ids);
    else
        num_path(blockIdx.x - BB * CLU, x, seqlens, num_logA, num_ls, num_lf, num_ids);
}

__global__ void finalize_kernel(float* __restrict__ out) {
    float sden = 0.f, snum = 0.f;
    for (int i = 0; i < BB; ++i) {
        sden += g_llh[i];
        snum += g_llh[BB + i];
    }
    out[0] = -(snum - sden);
}

extern "C" void kernel_launch(void* const* d_in, const int* in_sizes, int n_in,
                              void* d_out, int out_size) {
    const float* x        = (const float*)d_in[0];
    const int*   seqlens  = (const int*)d_in[1];
    const float* num_logA = (const float*)d_in[2];
    const float* num_ls   = (const float*)d_in[3];
    const float* num_lf   = (const float*)d_in[4];
    const int*   num_ids  = (const int*)d_in[5];
    const float* den_logA = (const float*)d_in[6];
    const float* den_ls   = (const float*)d_in[7];
    const float* den_lf   = (const float*)d_in[8];
    const int*   den_ids  = (const int*)d_in[9];

    fused_kernel<<<BB * CLU + BB, 512>>>(x, seqlens, num_logA, num_ls, num_lf,
                                         num_ids, den_logA, den_ls, den_lf, den_ids);
    finalize_kernel<<<1, 1>>>((float*)d_out);
}

// round 10
// speedup vs baseline: 2.2214x; 1.1721x over previous
#include <cuda_runtime.h>
#include <cstdint>
#include <math.h>

#define BB 16
#define TT 500
#define CC 2048
#define SN 64
#define SD 512
#define CLU 8                      // CTAs per den cluster
#define CPC (SD / CLU)             // 64 columns per den CTA

typedef unsigned long long ull;

__device__ float g_llh[2 * BB];    // [0..15] den, [16..31] num
__device__ int g_done;             // producer completion counter (self-resetting)

__device__ __forceinline__ float warp_max(float v) {
#pragma unroll
    for (int o = 16; o > 0; o >>= 1) v = fmaxf(v, __shfl_xor_sync(0xffffffffu, v, o));
    return v;
}
__device__ __forceinline__ float warp_sum(float v) {
#pragma unroll
    for (int o = 16; o > 0; o >>= 1) v += __shfl_xor_sync(0xffffffffu, v, o);
    return v;
}
__device__ __forceinline__ float clip30(float v) {
    return fminf(fmaxf(v, -30.f), 30.f);
}
__device__ __forceinline__ uint32_t smem_u32(const void* p) {
    uint32_t a;
    asm("{ .reg .u64 t; cvta.to.shared.u64 t, %1; cvt.u32.u64 %0, t; }" : "=r"(a) : "l"(p));
    return a;
}
// inline mapa + remote store (proven pattern)
__device__ __forceinline__ void st_cluster_f32(uint32_t local_addr, int rank, float v) {
    uint32_t rem;
    asm volatile("mapa.shared::cluster.u32 %0, %1, %2;" : "=r"(rem) : "r"(local_addr), "r"(rank));
    asm volatile("st.shared::cluster.f32 [%0], %1;" :: "r"(rem), "f"(v) : "memory");
}
__device__ __forceinline__ void st_cluster_u64(uint32_t local_addr, int rank, ull v) {
    uint32_t rem;
    asm volatile("mapa.shared::cluster.u32 %0, %1, %2;" : "=r"(rem) : "r"(local_addr), "r"(rank));
    asm volatile("st.shared::cluster.u64 [%0], %1;" :: "r"(rem), "l"(v) : "memory");
}
__device__ __forceinline__ void cluster_sync_() {
    asm volatile("barrier.cluster.arrive.aligned;" ::: "memory");
    asm volatile("barrier.cluster.wait.aligned;" ::: "memory");
}
__device__ __forceinline__ uint32_t ctarank_() {
    uint32_t r;
    asm("mov.u32 %0, %%cluster_ctarank;" : "=r"(r));
    return r;
}
// packed dual-fp32 fma: d = a * b + d
__device__ __forceinline__ void fma2(ull& d, ull a, ull b) {
    asm("fma.rn.f32x2 %0, %1, %2, %0;" : "+l"(d) : "l"(a), "l"(b));
}

// ---------------------------------------------------------------------------
// Denominator: one 8-CTA cluster per batch, linear state, output-side norm:
//   w_t[j] = (sum_s w_{t-1}[s] P[s,j]) * (1/max(w_{t-1})) * exp(em_t[j])
// Per step: matvec (all 512, on raw pushed {w,w}) -> ONE __syncthreads ->
// producer-only finalize (64 threads: reduce, scale, push u64 x8, push max)
// -> cluster.sync. All per-step MUFU/LDS/push work confined to producers.
// ---------------------------------------------------------------------------
__device__ void den_path(const float* __restrict__ x, const int* __restrict__ seqlens,
                         const float* __restrict__ logA, const float* __restrict__ ls,
                         const float* __restrict__ lf, const int* __restrict__ ids_g) {
    __shared__ __align__(16) ull u2buf[2][SD];       // packed {w,w}, double-buffered
    __shared__ __align__(16) ull red2[16 * 32];      // [rg][cp] -> cols {2cp,2cp+1}
    __shared__ float m_arr[2][16];                   // [src CTA r][producer warp]
    __shared__ float warp_red[16];

    const int tid  = threadIdx.x;
    const int lane = tid & 31, wid = tid >> 5;
    const int rg   = tid >> 5;          // matvec row group 0..15 (32 rows each)
    const int cp   = tid & 31;          // matvec column pair 0..31
    const int r    = (int)ctarank_();
    const int b    = blockIdx.x / CLU;
    const int j0   = r * CPC + 2 * cp;
    const int L    = seqlens[b];
    const float* xb = x + (size_t)b * TT * CC;

    // P slice in registers, packed per column pair
    ull pr[32];
#pragma unroll
    for (int k = 0; k < 32; ++k) {
        float2 p2;
        p2.x = __expf(logA[(size_t)(rg * 32 + k) * SD + j0]);
        p2.y = __expf(logA[(size_t)(rg * 32 + k) * SD + j0 + 1]);
        pr[k] = *(ull*)&p2;
    }

    // t = 0 init (threads 0..63 own this CTA's 64 columns)
    int myid = 0;
    float emn = 0.f, logC = 0.f;
    const int jcol = r * CPC + tid;     // valid when tid < 64
    if (tid < 64) {
        myid = ids_g[jcol];
        float w0 = __expf(ls[jcol] + clip30(xb[myid]));
        float2 ww0 = make_float2(w0, w0);
        ull wp0 = *(ull*)&ww0;
#pragma unroll
        for (int q = 0; q < CLU; ++q)
            st_cluster_u64(smem_u32(&u2buf[0][jcol]), q, wp0);
        float wm = warp_max(w0);
        if (lane == 0) {
#pragma unroll
            for (int q = 0; q < CLU; ++q)
                st_cluster_f32(smem_u32(&m_arr[0][r * 2 + wid]), q, wm);
        }
        emn = (L > 1) ? xb[CC + myid] : 0.f;
    }
    cluster_sync_();

    int p = 0;
    for (int t = 1; t < L; ++t) {
        // matvec partial: 32 rows x 2 cols, packed f32x2, direct on u2buf[p]
        ull acc = 0ull;
        const ulonglong2* uu = (const ulonglong2*)&u2buf[p][rg * 32];
#pragma unroll
        for (int k2 = 0; k2 < 16; ++k2) {
            ulonglong2 u = uu[k2];
            fma2(acc, u.x, pr[2 * k2]);
            fma2(acc, u.y, pr[2 * k2 + 1]);
        }
        red2[rg * 32 + cp] = acc;
        // producer-only prep, overlapped with other warps' matvec tail
        float E = 0.f, sc = 0.f, m = 0.f;
        if (tid < 64) {
            E = __expf(clip30(emn));
            if (t + 1 < L) emn = xb[(size_t)(t + 1) * CC + myid];
            m = m_arr[p][0];
#pragma unroll
            for (int i = 1; i < 16; ++i) m = fmaxf(m, m_arr[p][i]);
            sc = __fdividef(1.0f, m);
        }
        __syncthreads();

        if (tid < 64) {
            // reduce 16 partials for my col (4-way trees)
            const float* rf = (const float*)red2;
            float v0 = 0.f, v1 = 0.f, v2 = 0.f, v3 = 0.f;
#pragma unroll
            for (int g2 = 0; g2 < 4; ++g2) {
                v0 += rf[(4 * g2 + 0) * 64 + tid];
                v1 += rf[(4 * g2 + 1) * 64 + tid];
                v2 += rf[(4 * g2 + 2) * 64 + tid];
                v3 += rf[(4 * g2 + 3) * 64 + tid];
            }
            float w = (((v0 + v1) + (v2 + v3)) * sc) * E;   // bounded in fp32
            float2 ww = make_float2(w, w);
            ull wp2 = *(ull*)&ww;
#pragma unroll
            for (int q = 0; q < CLU; ++q)
                st_cluster_u64(smem_u32(&u2buf[1 - p][jcol]), q, wp2);
            float wm = warp_max(w);
            if (lane == 0) {
#pragma unroll
                for (int q = 0; q < CLU; ++q)
                    st_cluster_f32(smem_u32(&m_arr[1 - p][r * 2 + wid]), q, wm);
            }
            if (tid == 0) logC += __logf(m);
        }
        cluster_sync_();
        p ^= 1;
    }

    // llh = logC + log(sum_j w[j] * exp(lf[j]));  rank 0 has full w
    if (r == 0) {
        float w = __uint_as_float((uint32_t)u2buf[p][tid]);   // low half
        float e = w * __expf(lf[tid]);
        float ws = warp_sum(e);
        if (lane == 0) warp_red[wid] = ws;
        __syncthreads();
        if (tid == 0) {
            float s = 0.f;
            for (int i = 0; i < 16; ++i) s += warp_red[i];
            g_llh[b] = logC + __logf(s);
            __threadfence();
            atomicAdd(&g_done, 1);
        }
    }
    cluster_sync_();   // no CTA exits while peers may still receive DSMEM traffic
}

// ---------------------------------------------------------------------------
// Numerator: per-batch FSM (S=64), linear state, one CTA per batch (hidden).
// ---------------------------------------------------------------------------
__device__ void num_path(int b, const float* __restrict__ x,
                         const int* __restrict__ seqlens,
                         const float* __restrict__ logA,
                         const float* __restrict__ ls,
                         const float* __restrict__ lf,
                         const int* __restrict__ ids_g) {
    __shared__ __align__(16) float Pn[SN * SN];
    __shared__ float w_n[SN];
    __shared__ float redn[8][SN];
    __shared__ float wred[2];

    const int tid = threadIdx.x;
    const int lane = tid & 31;
    const int g = tid >> 6;              // row group 0..7 (8 rows each)
    const int col = tid & 63;
    const int L = seqlens[b];
    const float* xb = x + (size_t)b * TT * CC;

    for (int i = tid; i < SN * SN; i += 512)
        Pn[i] = __expf(logA[(size_t)b * SN * SN + i]);

    int myid = 0;
    float emn = 0.f, logC = 0.f;
    if (tid < SN) {
        myid = ids_g[b * SN + tid];
        float w0 = __expf(ls[b * SN + tid] + clip30(xb[myid]));
        w_n[tid] = w0;
        float wm = warp_max(w0);
        if (lane == 0) wred[tid >> 5] = wm;
        emn = (L > 1) ? xb[CC + myid] : 0.f;
    }
    __syncthreads();

    for (int t = 1; t < L; ++t) {
        float m = fmaxf(wred[0], wred[1]);
        float E = 0.f, sc = 0.f;
        if (tid < SN) {
            sc = __fdividef(1.0f, m);
            E = __expf(clip30(emn));
            if (t + 1 < L) emn = xb[(size_t)(t + 1) * CC + myid];
        }
        float acc = 0.f;
#pragma unroll
        for (int k = 0; k < 8; ++k)
            acc = fmaf(w_n[g * 8 + k], Pn[(g * 8 + k) * SN + col], acc);
        redn[g][col] = acc;
        __syncthreads();
        if (tid < SN) {
            float v = 0.f;
#pragma unroll
            for (int g2 = 0; g2 < 8; ++g2) v += redn[g2][tid];
            float w = (v * sc) * E;
            w_n[tid] = w;
            float wm = warp_max(w);
            if (lane == 0) wred[tid >> 5] = wm;
            if (tid == 0) logC += __logf(m);
        }
        __syncthreads();
    }

    if (tid < SN) {
        float e = w_n[tid] * __expf(lf[b * SN + tid]);
        float ws = warp_sum(e);
        if (lane == 0) wred[tid >> 5] = ws;
    }
    __syncthreads();
    if (tid == 0) {
        g_llh[BB + b] = logC + __logf(wred[0] + wred[1]);
        __threadfence();
        atomicAdd(&g_done, 1);
    }
}

// Fused: clusters 0..15 (CTAs 0..127) = den; CTAs 128..143 = num batches 0..15.
// CTA 143 additionally finalizes the output (spin on producer counter), so
// the whole problem is ONE launch.
__global__ void __launch_bounds__(512, 1) __cluster_dims__(CLU, 1, 1)
fused_kernel(const float* __restrict__ x, const int* __restrict__ seqlens,
             const float* __restrict__ num_logA, const float* __restrict__ num_ls,
             const float* __restrict__ num_lf, const int* __restrict__ num_ids,
             const float* __restrict__ den_logA, const float* __restrict__ den_ls,
             const float* __restrict__ den_lf, const int* __restrict__ den_ids,
             float* __restrict__ out) {
    if (blockIdx.x < BB * CLU) {
        den_path(x, seqlens, den_logA, den_ls, den_lf, den_ids);
    } else {
        num_path(blockIdx.x - BB * CLU, x, seqlens, num_logA, num_ls, num_lf, num_ids);
        if (blockIdx.x == BB * CLU + BB - 1 && threadIdx.x == 0) {
            while (atomicAdd(&g_done, 0) < 2 * BB) {}
            __threadfence();
            float sden = 0.f, snum = 0.f;
            for (int i = 0; i < BB; ++i) {
                sden += g_llh[i];
                snum += g_llh[BB + i];
            }
            out[0] = -(snum - sden);
            atomicSub(&g_done, 2 * BB);   // reset for next graph replay
        }
    }
}

extern "C" void kernel_launch(void* const* d_in, const int* in_sizes, int n_in,
                              void* d_out, int out_size) {
    const float* x        = (const float*)d_in[0];
    const int*   seqlens  = (const int*)d_in[1];
    const float* num_logA = (const float*)d_in[2];
    const float* num_ls   = (const float*)d_in[3];
    const float* num_lf   = (const float*)d_in[4];
    const int*   num_ids  = (const int*)d_in[5];
    const float* den_logA = (const float*)d_in[6];
    const float* den_ls   = (const float*)d_in[7];
    const float* den_lf   = (const float*)d_in[8];
    const int*   den_ids  = (const int*)d_in[9];

    fused_kernel<<<BB * CLU + BB, 512>>>(x, seqlens, num_logA, num_ls, num_lf,
                                         num_ids, den_logA, den_ls, den_lf,
                                         den_ids, (float*)d_out);
}